// round 11
// baseline (speedup 1.0000x reference)
#include <cuda_runtime.h>
#include <cuda_fp16.h>
#include <math.h>
#include <stdint.h>

#define D_IN 1024
#define NHEAD 16
#define NHID 64
#define BATCH 2
#define SEQ 2048
#define MTOT (BATCH * SEQ)   /* 4096 */
#define NTOT (NHEAD * NHID)  /* 1024 */
#define BH (BATCH * NHEAD)   /* 32 */
#define DPAIRS (NHID / 2)    /* 32 */
#define SPAIRS (SEQ / 2)     /* 1024 */
#define XW 512               /* pair-words per row of X/W planes */

// fp16 pair-packed planes, k-pairs permuted [p0,p4,p1,p5,p2,p6,p3,p7] per 8-group.
__device__ uint32_t g_Xh[(size_t)3 * MTOT * XW];
__device__ uint32_t g_Xl[(size_t)3 * MTOT * XW];
__device__ uint32_t g_Wh[(size_t)3 * NTOT * XW];
__device__ uint32_t g_Wl[(size_t)3 * NTOT * XW];
// Q/K: (B,H,S,Dh-pairs) split planes (Q pre-scaled by 0.125). V: (B,H,Dh,S-pairs) hi only.
__device__ uint32_t g_Qh[(size_t)BH * SEQ * DPAIRS];
__device__ uint32_t g_Ql[(size_t)BH * SEQ * DPAIRS];
__device__ uint32_t g_Kh[(size_t)BH * SEQ * DPAIRS];
__device__ uint32_t g_Kl[(size_t)BH * SEQ * DPAIRS];
__device__ uint32_t g_VTh[(size_t)BH * NHID * SPAIRS];

// ---------------------------------------------------------------------------
__device__ __forceinline__ int permpos(int p) { return p < 4 ? 2 * p : 2 * p - 7; }

__device__ __forceinline__ uint32_t f2h2(float a, float b) {
    __half2 h = __float22half2_rn(make_float2(a, b));
    return *reinterpret_cast<uint32_t*>(&h);
}
__device__ __forceinline__ void split_h(float a, float b, uint32_t& h, uint32_t& l) {
    __half2 H = __float22half2_rn(make_float2(a, b));
    float2 Hf = __half22float2(H);
    __half2 L = __float22half2_rn(make_float2(a - Hf.x, b - Hf.y));
    h = *reinterpret_cast<uint32_t*>(&H);
    l = *reinterpret_cast<uint32_t*>(&L);
}
__device__ __forceinline__ void mma_fp16(float* d, const uint32_t* a, uint2 b) {
    asm volatile(
        "mma.sync.aligned.m16n8k16.row.col.f32.f16.f16.f32 "
        "{%0,%1,%2,%3}, {%4,%5,%6,%7}, {%8,%9}, {%0,%1,%2,%3};\n"
        : "+f"(d[0]), "+f"(d[1]), "+f"(d[2]), "+f"(d[3])
        : "r"(a[0]), "r"(a[1]), "r"(a[2]), "r"(a[3]), "r"(b.x), "r"(b.y));
}
__device__ __forceinline__ void cp_async16(uint32_t dst, const void* src) {
    asm volatile("cp.async.cg.shared.global [%0], [%1], 16;\n" :: "r"(dst), "l"(src));
}
__device__ __forceinline__ void cp_commit() { asm volatile("cp.async.commit_group;\n"); }
template <int N>
__device__ __forceinline__ void cp_wait() { asm volatile("cp.async.wait_group %0;\n" :: "n"(N)); }

// ---------------------------------------------------------------------------
// Prep: split X/W into fp16 pair planes, permuted. float4 per thread (2 pairs).
// ---------------------------------------------------------------------------
#define XTOT4 (3 * MTOT * (XW / 2))  /* 3145728 */
#define WTOT4 (3 * NTOT * (XW / 2))  /* 786432 */
#define PREP_BLOCKS ((XTOT4 + WTOT4) / 256)  /* 15360 */

__global__ __launch_bounds__(256) void prep_split(
    const float* __restrict__ xq, const float* __restrict__ xk, const float* __restrict__ xv,
    const float* __restrict__ wq, const float* __restrict__ wk, const float* __restrict__ wv)
{
    const int idx = blockIdx.x * 256 + threadIdx.x;
    const float* src;
    uint32_t *dh, *dl;
    int row, p4;
    if (idx < XTOT4) {
        const int z = idx / (MTOT * (XW / 2));
        const int r = idx - z * (MTOT * (XW / 2));
        row = r >> 8; p4 = r & 255;
        src = ((z == 0) ? xq : (z == 1) ? xk : xv) + (size_t)row * D_IN;
        dh = g_Xh + (size_t)z * MTOT * XW + (size_t)row * XW;
        dl = g_Xl + (size_t)z * MTOT * XW + (size_t)row * XW;
    } else {
        const int r2 = idx - XTOT4;
        const int z = r2 / (NTOT * (XW / 2));
        const int r = r2 - z * (NTOT * (XW / 2));
        row = r >> 8; p4 = r & 255;
        src = ((z == 0) ? wq : (z == 1) ? wk : wv) + (size_t)row * D_IN;
        dh = g_Wh + (size_t)z * NTOT * XW + (size_t)row * XW;
        dl = g_Wl + (size_t)z * NTOT * XW + (size_t)row * XW;
    }
    float4 v = *(const float4*)(src + 4 * p4);
    uint32_t h0, l0, h1, l1;
    split_h(v.x, v.y, h0, l0);
    split_h(v.z, v.w, h1, l1);
    const int p0 = 2 * p4, p1 = 2 * p4 + 1;
    const int w0 = (p0 & ~7) + permpos(p0 & 7);
    const int w1 = (p1 & ~7) + permpos(p1 & 7);
    dh[w0] = h0; dl[w0] = l0;
    dh[w1] = h1; dl[w1] = l1;
}

// ---------------------------------------------------------------------------
// Fused QKV GEMM, fp16 3-term (AhBh + AlBh + AhBl). Block 256x128, ktile 32,
// 8 warps (64m x 64n), cp.async double-buffered pre-split planes.
// Plane row stride 24 words (16 data + 8 pad; conflict-free LDS.64 fragments).
// ---------------------------------------------------------------------------
#define G_STRIDE 24
#define A_TILE (256 * G_STRIDE)            /* 6144 words */
#define B_TILE (128 * G_STRIDE)            /* 3072 words */
#define O_AH 0
#define O_AL (2 * A_TILE)
#define O_BH (4 * A_TILE)
#define O_BL (4 * A_TILE + 2 * B_TILE)
#define GEMM_MAIN_WORDS (4 * A_TILE + 4 * B_TILE)  /* 36864 */
#define TS_LD 130
#define GEMM_SMEM_BYTES (GEMM_MAIN_WORDS * 4)      /* 147456 */

__global__ __launch_bounds__(256, 1) void qkv_gemm_fp16(
    const float* __restrict__ bq, const float* __restrict__ bk, const float* __restrict__ bv)
{
    extern __shared__ uint32_t smw[];
    const int z = blockIdx.z;
    const float* bias = (z == 0) ? bq : (z == 1) ? bk : bv;

    const int tid = threadIdx.x;
    const int bm = blockIdx.y * 256;
    const int bn = blockIdx.x * 128;
    const int warp = tid >> 5, lane = tid & 31;
    const int g = lane >> 2, t = lane & 3;
    const int wm = (warp >> 1) * 64;
    const int wn = (warp & 1) * 64;

    const uint32_t smBase = (uint32_t)__cvta_generic_to_shared(smw);
    const int r0 = tid >> 2;             // 0..63
    const int woff = (tid & 3) * 4;      // 0,4,8,12

    const uint32_t* Axh = g_Xh + (size_t)z * MTOT * XW + (size_t)bm * XW;
    const uint32_t* Axl = g_Xl + (size_t)z * MTOT * XW + (size_t)bm * XW;
    const uint32_t* Bwh = g_Wh + (size_t)z * NTOT * XW + (size_t)bn * XW;
    const uint32_t* Bwl = g_Wl + (size_t)z * NTOT * XW + (size_t)bn * XW;

#define GEMM_ISSUE(KT) do {                                                      \
    const int _buf = (KT) & 1;                                                   \
    _Pragma("unroll")                                                            \
    for (int _grp = 0; _grp < 4; _grp++) {                                       \
        const int _row = _grp * 64 + r0;                                         \
        cp_async16(smBase + (O_AH + _buf * A_TILE + _row * G_STRIDE + woff) * 4, \
                   Axh + (size_t)_row * XW + (KT) * 16 + woff);                  \
        cp_async16(smBase + (O_AL + _buf * A_TILE + _row * G_STRIDE + woff) * 4, \
                   Axl + (size_t)_row * XW + (KT) * 16 + woff);                  \
    }                                                                            \
    _Pragma("unroll")                                                            \
    for (int _grp = 0; _grp < 2; _grp++) {                                       \
        const int _row = _grp * 64 + r0;                                         \
        cp_async16(smBase + (O_BH + _buf * B_TILE + _row * G_STRIDE + woff) * 4, \
                   Bwh + (size_t)_row * XW + (KT) * 16 + woff);                  \
        cp_async16(smBase + (O_BL + _buf * B_TILE + _row * G_STRIDE + woff) * 4, \
                   Bwl + (size_t)_row * XW + (KT) * 16 + woff);                  \
    }                                                                            \
    cp_commit();                                                                 \
} while (0)

    float acc[4][8][4];
#pragma unroll
    for (int mt = 0; mt < 4; mt++)
#pragma unroll
        for (int j = 0; j < 8; j++)
#pragma unroll
            for (int c = 0; c < 4; c++) acc[mt][j][c] = 0.0f;

    GEMM_ISSUE(0);
    GEMM_ISSUE(1);

    const int NKT = D_IN / 32;  // 32
    for (int kt = 0; kt < NKT; kt++) {
        if (kt == NKT - 1) cp_wait<0>(); else cp_wait<1>();
        __syncthreads();
        const int buf = kt & 1;
        const uint32_t* Ahb = smw + O_AH + buf * A_TILE;
        const uint32_t* Alb = smw + O_AL + buf * A_TILE;
        const uint32_t* Bhb = smw + O_BH + buf * B_TILE;
        const uint32_t* Blb = smw + O_BL + buf * B_TILE;
#pragma unroll
        for (int ks = 0; ks < 2; ks++) {
            uint32_t ah[4][4], al[4][4];
#pragma unroll
            for (int mt = 0; mt < 4; mt++) {
                const uint32_t* p = Ahb + (wm + mt * 16 + g) * G_STRIDE + ks * 8 + 2 * t;
                uint2 x0 = *(const uint2*)p;
                uint2 x1 = *(const uint2*)(p + 8 * G_STRIDE);
                ah[mt][0] = x0.x; ah[mt][1] = x1.x; ah[mt][2] = x0.y; ah[mt][3] = x1.y;
                const uint32_t* q = Alb + (wm + mt * 16 + g) * G_STRIDE + ks * 8 + 2 * t;
                uint2 y0 = *(const uint2*)q;
                uint2 y1 = *(const uint2*)(q + 8 * G_STRIDE);
                al[mt][0] = y0.x; al[mt][1] = y1.x; al[mt][2] = y0.y; al[mt][3] = y1.y;
            }
#pragma unroll
            for (int j = 0; j < 8; j++) {
                uint2 bh = *(const uint2*)(Bhb + (wn + j * 8 + g) * G_STRIDE + ks * 8 + 2 * t);
                uint2 bl = *(const uint2*)(Blb + (wn + j * 8 + g) * G_STRIDE + ks * 8 + 2 * t);
#pragma unroll
                for (int mt = 0; mt < 4; mt++) {
                    mma_fp16(acc[mt][j], ah[mt], bh);
                    mma_fp16(acc[mt][j], al[mt], bh);
                    mma_fp16(acc[mt][j], ah[mt], bl);
                }
            }
        }
        __syncthreads();
        if (kt + 2 < NKT) GEMM_ISSUE(kt + 2);
    }

    float bv2[8][2];
#pragma unroll
    for (int j = 0; j < 8; j++) {
        const int n = bn + wn + j * 8 + 2 * t;
        bv2[j][0] = bias[n];
        bv2[j][1] = bias[n + 1];
    }

    if (z < 2) {
        uint32_t* PH = (z == 0) ? g_Qh : g_Kh;
        uint32_t* PL = (z == 0) ? g_Ql : g_Kl;
        const float scale = (z == 0) ? 0.125f : 1.0f;
        const int head = (bn + wn) >> 6;
#pragma unroll
        for (int mt = 0; mt < 4; mt++)
#pragma unroll
            for (int half = 0; half < 2; half++) {
                const int m = bm + wm + mt * 16 + half * 8 + g;
                const int b = m >> 11;
                const int s = m & (SEQ - 1);
                const size_t base = ((size_t)(b * NHEAD + head) * SEQ + s) * DPAIRS;
#pragma unroll
                for (int j = 0; j < 8; j++) {
                    float v0 = (acc[mt][j][half * 2 + 0] + bv2[j][0]) * scale;
                    float v1 = (acc[mt][j][half * 2 + 1] + bv2[j][1]) * scale;
                    uint32_t hw, lw;
                    split_h(v0, v1, hw, lw);
                    const int word = (j >> 1) * 8 + 2 * t + (j & 1);
                    PH[base + word] = hw;
                    PL[base + word] = lw;
                }
            }
    } else {
        // V: fp32 transpose through smem, store hi plane only, (B,H,Dh,S-pairs).
        float* Ts = (float*)smw;
        __syncthreads();
#pragma unroll
        for (int mt = 0; mt < 4; mt++)
#pragma unroll
            for (int half = 0; half < 2; half++) {
                const int ml = wm + mt * 16 + half * 8 + g;
#pragma unroll
                for (int j = 0; j < 8; j++) {
                    const int nl = wn + j * 8 + 2 * t;
                    Ts[ml * TS_LD + nl]     = acc[mt][j][half * 2 + 0] + bv2[j][0];
                    Ts[ml * TS_LD + nl + 1] = acc[mt][j][half * 2 + 1] + bv2[j][1];
                }
            }
        __syncthreads();
        const int b = bm >> 11;
        const int sloc = bm & (SEQ - 1);
#pragma unroll
        for (int i = 0; i < 64; i++) {
            const int linear = i * 256 + tid;     // 16384 pair-elements
            const int dloc = linear >> 7;         // 0..127
            const int sp = linear & 127;          // s-pair within 256-row tile
            const float v0 = Ts[(2 * sp) * TS_LD + dloc];
            const float v1 = Ts[(2 * sp + 1) * TS_LD + dloc];
            const int dg = bn + dloc;
            const int h = dg >> 6, dh = dg & 63;
            const int aps = (sloc >> 1) + sp;
            const int word = (aps & ~7) + permpos(sp & 7);
            g_VTh[((size_t)(b * NHEAD + h) * NHID + dh) * SPAIRS + word] = f2h2(v0, v1);
        }
    }
#undef GEMM_ISSUE
}

// ---------------------------------------------------------------------------
// Flash attention, fp16. BQ=256, BKV=64, 8 warps (32q x 64kv, mt=2), 1 CTA/SM.
// QK 3-term (QhKh + QlKh + QhKl); PV 1-term (P fp16 single x Vh single).
// Row stride 40 words (conflict-free LDS.64).
// ---------------------------------------------------------------------------
#define A_STRIDE 40
#define QW (256 * A_STRIDE)      /* 10240 words per Q plane */
#define KVW (64 * A_STRIDE)      /* 2560 words per KV plane per buffer */
#define O_QH 0
#define O_QL QW
#define O_KH (2 * QW)                 /* 20480 */
#define O_KL (2 * QW + 2 * KVW)       /* 25600 */
#define O_VH (2 * QW + 4 * KVW)       /* 30720 */
#define ATT_SMEM_WORDS (2 * QW + 6 * KVW)   /* 35840 */
#define ATT_SMEM_BYTES (ATT_SMEM_WORDS * 4) /* 143360 */

__device__ __forceinline__ void attn_stage_kv(const uint32_t* Kh, const uint32_t* Kl,
                                              const uint32_t* Vh,
                                              uint32_t smBase, int tid, int it) {
    const int buf = it & 1;
    const int kv0 = it * 64;
#pragma unroll
    for (int i = 0; i < 2; i++) {
        const int row = i * 32 + (tid >> 3);       // 0..63
        const int off = (tid & 7) * 4;             // word offset in 32-word row
        const uint32_t d = smBase + (buf * KVW + row * A_STRIDE + off) * 4;
        cp_async16(d + O_KH * 4, Kh + (size_t)(kv0 + row) * DPAIRS + off);
        cp_async16(d + O_KL * 4, Kl + (size_t)(kv0 + row) * DPAIRS + off);
        cp_async16(d + O_VH * 4, Vh + (size_t)row * SPAIRS + it * DPAIRS + off);
    }
    cp_commit();
}

__global__ __launch_bounds__(256, 1) void attn_fp16(float* __restrict__ out)
{
    extern __shared__ uint32_t smw[];

    const int tid = threadIdx.x;
    const int warp = tid >> 5, lane = tid & 31;
    const int g = lane >> 2, t = lane & 3;
    const int bh = blockIdx.y;
    const int q0 = blockIdx.x * 256;
    const int wq = warp * 32;

    const uint32_t* Qh = g_Qh + ((size_t)bh * SEQ + q0) * DPAIRS;
    const uint32_t* Ql = g_Ql + ((size_t)bh * SEQ + q0) * DPAIRS;
    const uint32_t* Kh = g_Kh + (size_t)bh * SEQ * DPAIRS;
    const uint32_t* Kl = g_Kl + (size_t)bh * SEQ * DPAIRS;
    const uint32_t* Vh = g_VTh + (size_t)bh * NHID * SPAIRS;

    const uint32_t smBase = (uint32_t)__cvta_generic_to_shared(smw);

    // Q tile: 256 rows x 32 words x 2 planes = 2048 16B chunks per plane.
#pragma unroll
    for (int i = 0; i < 8; i++) {
        const int c = tid + 256 * i;   // 0..2047 per plane
        const int row = c >> 3;
        const int off = (c & 7) * 4;
        cp_async16(smBase + (O_QH + row * A_STRIDE + off) * 4, Qh + (size_t)row * DPAIRS + off);
        cp_async16(smBase + (O_QL + row * A_STRIDE + off) * 4, Ql + (size_t)row * DPAIRS + off);
    }
    attn_stage_kv(Kh, Kl, Vh, smBase, tid, 0);   // group 0 = Q + KV0
    attn_stage_kv(Kh, Kl, Vh, smBase, tid, 1);   // group 1

    float m_i[4], l_i[4], O[2][8][4];
#pragma unroll
    for (int r = 0; r < 4; r++) { m_i[r] = -INFINITY; l_i[r] = 0.0f; }
#pragma unroll
    for (int mt = 0; mt < 2; mt++)
#pragma unroll
        for (int j = 0; j < 8; j++)
#pragma unroll
            for (int c = 0; c < 4; c++) O[mt][j][c] = 0.0f;

    const int NIT = SEQ / 64;  // 32
    for (int it = 0; it < NIT; it++) {
        if (it == NIT - 1) cp_wait<0>(); else cp_wait<1>();
        __syncthreads();
        const int buf = it & 1;
        const uint32_t* Khb = smw + O_KH + buf * KVW;
        const uint32_t* Klb = smw + O_KL + buf * KVW;
        const uint32_t* Vhb = smw + O_VH + buf * KVW;

        // ---- S = Q K^T (3-term), mt=2 ----
        float S[2][8][4];
#pragma unroll
        for (int mt = 0; mt < 2; mt++)
#pragma unroll
            for (int j = 0; j < 8; j++)
#pragma unroll
                for (int c = 0; c < 4; c++) S[mt][j][c] = 0.0f;

#pragma unroll
        for (int ks = 0; ks < 4; ks++) {
            uint32_t qh[2][4], ql[2][4];
#pragma unroll
            for (int mt = 0; mt < 2; mt++) {
                const uint32_t* p = smw + O_QH + (wq + mt * 16 + g) * A_STRIDE + ks * 8 + 2 * t;
                uint2 x0 = *(const uint2*)p;
                uint2 x1 = *(const uint2*)(p + 8 * A_STRIDE);
                qh[mt][0] = x0.x; qh[mt][1] = x1.x; qh[mt][2] = x0.y; qh[mt][3] = x1.y;
                const uint32_t* q = smw + O_QL + (wq + mt * 16 + g) * A_STRIDE + ks * 8 + 2 * t;
                uint2 y0 = *(const uint2*)q;
                uint2 y1 = *(const uint2*)(q + 8 * A_STRIDE);
                ql[mt][0] = y0.x; ql[mt][1] = y1.x; ql[mt][2] = y0.y; ql[mt][3] = y1.y;
            }
#pragma unroll
            for (int j = 0; j < 8; j++) {
                uint2 kh = *(const uint2*)(Khb + (j * 8 + g) * A_STRIDE + ks * 8 + 2 * t);
                uint2 kl = *(const uint2*)(Klb + (j * 8 + g) * A_STRIDE + ks * 8 + 2 * t);
#pragma unroll
                for (int mt = 0; mt < 2; mt++) {
                    mma_fp16(S[mt][j], qh[mt], kh);
                    mma_fp16(S[mt][j], ql[mt], kh);
                    mma_fp16(S[mt][j], qh[mt], kl);
                }
            }
        }

        // ---- online softmax (4 rows per thread; shfl over t) ----
#pragma unroll
        for (int mt = 0; mt < 2; mt++) {
#pragma unroll
            for (int half = 0; half < 2; half++) {
                const int ri = mt * 2 + half;
                float mx = -INFINITY;
#pragma unroll
                for (int j = 0; j < 8; j++)
                    mx = fmaxf(mx, fmaxf(S[mt][j][half * 2], S[mt][j][half * 2 + 1]));
                mx = fmaxf(mx, __shfl_xor_sync(0xffffffffu, mx, 1));
                mx = fmaxf(mx, __shfl_xor_sync(0xffffffffu, mx, 2));
                const float mn = fmaxf(m_i[ri], mx);
                const float corr = __expf(m_i[ri] - mn);
                m_i[ri] = mn;
                float rs = 0.0f;
#pragma unroll
                for (int j = 0; j < 8; j++) {
                    const float e0 = __expf(S[mt][j][half * 2]     - mn);
                    const float e1 = __expf(S[mt][j][half * 2 + 1] - mn);
                    S[mt][j][half * 2]     = e0;
                    S[mt][j][half * 2 + 1] = e1;
                    rs += e0 + e1;
                }
                rs += __shfl_xor_sync(0xffffffffu, rs, 1);
                rs += __shfl_xor_sync(0xffffffffu, rs, 2);
                l_i[ri] = l_i[ri] * corr + rs;
#pragma unroll
                for (int j = 0; j < 8; j++) {
                    O[mt][j][half * 2]     *= corr;
                    O[mt][j][half * 2 + 1] *= corr;
                }
            }
        }

        // ---- O += P V (P single fp16 from S regs; V hi plane), mt=2 ----
#pragma unroll
        for (int ks = 0; ks < 4; ks++) {
            uint32_t pf[2][4];
#pragma unroll
            for (int mt = 0; mt < 2; mt++) {
                pf[mt][0] = f2h2(S[mt][2 * ks][0],     S[mt][2 * ks][1]);
                pf[mt][1] = f2h2(S[mt][2 * ks][2],     S[mt][2 * ks][3]);
                pf[mt][2] = f2h2(S[mt][2 * ks + 1][0], S[mt][2 * ks + 1][1]);
                pf[mt][3] = f2h2(S[mt][2 * ks + 1][2], S[mt][2 * ks + 1][3]);
            }
#pragma unroll
            for (int j = 0; j < 8; j++) {
                uint2 vh = *(const uint2*)(Vhb + (j * 8 + g) * A_STRIDE + ks * 8 + 2 * t);
#pragma unroll
                for (int mt = 0; mt < 2; mt++)
                    mma_fp16(O[mt][j], pf[mt], vh);
            }
        }

        __syncthreads();
        if (it + 2 < NIT) attn_stage_kv(Kh, Kl, Vh, smBase, tid, it + 2);
    }

    // Epilogue: normalize, write (B, S, H*Dh).
    const int b = bh >> 4, h = bh & 15;
#pragma unroll
    for (int mt = 0; mt < 2; mt++)
#pragma unroll
        for (int half = 0; half < 2; half++) {
            const int ri = mt * 2 + half;
            const float inv = 1.0f / l_i[ri];
            const int q = q0 + wq + mt * 16 + half * 8 + g;
            float* orow = out + (size_t)(b * SEQ + q) * NTOT + h * NHID;
#pragma unroll
            for (int j = 0; j < 8; j++) {
                float2 v = make_float2(O[mt][j][half * 2] * inv,
                                       O[mt][j][half * 2 + 1] * inv);
                *(float2*)(orow + j * 8 + 2 * t) = v;
            }
        }
}

// ---------------------------------------------------------------------------
extern "C" void kernel_launch(void* const* d_in, const int* in_sizes, int n_in,
                              void* d_out, int out_size)
{
    const float* xq = (const float*)d_in[0];
    const float* xk = (const float*)d_in[1];
    const float* xv = (const float*)d_in[2];
    const float* wq = (const float*)d_in[3];
    const float* bq = (const float*)d_in[4];
    const float* wk = (const float*)d_in[5];
    const float* bk = (const float*)d_in[6];
    const float* wv = (const float*)d_in[7];
    const float* bv = (const float*)d_in[8];
    float* out = (float*)d_out;

    cudaFuncSetAttribute(qkv_gemm_fp16, cudaFuncAttributeMaxDynamicSharedMemorySize,
                         GEMM_SMEM_BYTES);
    cudaFuncSetAttribute(attn_fp16, cudaFuncAttributeMaxDynamicSharedMemorySize,
                         ATT_SMEM_BYTES);

    prep_split<<<PREP_BLOCKS, 256>>>(xq, xk, xv, wq, wk, wv);

    dim3 gg(NTOT / 128, MTOT / 256, 3);
    qkv_gemm_fp16<<<gg, 256, GEMM_SMEM_BYTES>>>(bq, bk, bv);

    dim3 ga(SEQ / 256, BH);
    attn_fp16<<<ga, 256, ATT_SMEM_BYTES>>>(out);
}

// round 13
// speedup vs baseline: 1.2658x; 1.2658x over previous
#include <cuda_runtime.h>
#include <cuda_fp16.h>
#include <math.h>
#include <stdint.h>

#define D_IN 1024
#define NHEAD 16
#define NHID 64
#define BATCH 2
#define SEQ 2048
#define MTOT (BATCH * SEQ)   /* 4096 */
#define NTOT (NHEAD * NHID)  /* 1024 */
#define BH (BATCH * NHEAD)   /* 32 */
#define DPAIRS (NHID / 2)    /* 32 */
#define SPAIRS (SEQ / 2)     /* 1024 */
#define XWQ 256              /* words (quads) per row of s8 planes */

// Quantization: value = (a*256 + b) / SCALE, SCALE = QMAX/LIM.
#define LIMX 6.0f
#define LIMW 0.26f
#define QMAX 32511.0f

// s8 planes, quad-permuted [q0,q4,q1,q5,q2,q6,q3,q7] per 8-quad (32-byte) group.
__device__ uint32_t g_Xa[(size_t)3 * MTOT * XWQ];
__device__ uint32_t g_Xb[(size_t)3 * MTOT * XWQ];
__device__ uint32_t g_Wa[(size_t)3 * NTOT * XWQ];
__device__ uint32_t g_Wb[(size_t)3 * NTOT * XWQ];
// Q/K: (B,H,S,Dh-pairs) fp16 split planes, pairs permuted (Q pre-scaled 0.125).
// V: (B,H,Dh,S-pairs) fp16 hi plane only, same permute. (Layouts identical to R7.)
__device__ uint32_t g_Qh[(size_t)BH * SEQ * DPAIRS];
__device__ uint32_t g_Ql[(size_t)BH * SEQ * DPAIRS];
__device__ uint32_t g_Kh[(size_t)BH * SEQ * DPAIRS];
__device__ uint32_t g_Kl[(size_t)BH * SEQ * DPAIRS];
__device__ uint32_t g_VTh[(size_t)BH * NHID * SPAIRS];

// ---------------------------------------------------------------------------
// helpers
// ---------------------------------------------------------------------------
__device__ __forceinline__ int permpos(int p) { return p < 4 ? 2 * p : 2 * p - 7; }

__device__ __forceinline__ uint32_t f2h2(float a, float b) {
    __half2 h = __float22half2_rn(make_float2(a, b));
    return *reinterpret_cast<uint32_t*>(&h);
}
__device__ __forceinline__ void split_h(float a, float b, uint32_t& h, uint32_t& l) {
    __half2 H = __float22half2_rn(make_float2(a, b));
    float2 Hf = __half22float2(H);
    __half2 L = __float22half2_rn(make_float2(a - Hf.x, b - Hf.y));
    h = *reinterpret_cast<uint32_t*>(&H);
    l = *reinterpret_cast<uint32_t*>(&L);
}
__device__ __forceinline__ void mma_fp16(float* d, const uint32_t* a, uint2 b) {
    asm volatile(
        "mma.sync.aligned.m16n8k16.row.col.f32.f16.f16.f32 "
        "{%0,%1,%2,%3}, {%4,%5,%6,%7}, {%8,%9}, {%0,%1,%2,%3};\n"
        : "+f"(d[0]), "+f"(d[1]), "+f"(d[2]), "+f"(d[3])
        : "r"(a[0]), "r"(a[1]), "r"(a[2]), "r"(a[3]), "r"(b.x), "r"(b.y));
}
__device__ __forceinline__ void mma_s8(int* d, const uint32_t* a, uint2 b) {
    asm volatile(
        "mma.sync.aligned.m16n8k32.row.col.s32.s8.s8.s32 "
        "{%0,%1,%2,%3}, {%4,%5,%6,%7}, {%8,%9}, {%0,%1,%2,%3};\n"
        : "+r"(d[0]), "+r"(d[1]), "+r"(d[2]), "+r"(d[3])
        : "r"(a[0]), "r"(a[1]), "r"(a[2]), "r"(a[3]), "r"(b.x), "r"(b.y));
}
__device__ __forceinline__ void cp_async16(uint32_t dst, const void* src) {
    asm volatile("cp.async.cg.shared.global [%0], [%1], 16;\n" :: "r"(dst), "l"(src));
}
__device__ __forceinline__ void cp_commit() { asm volatile("cp.async.commit_group;\n"); }
template <int N>
__device__ __forceinline__ void cp_wait() { asm volatile("cp.async.wait_group %0;\n" :: "n"(N)); }

// ---------------------------------------------------------------------------
// Prep: quantize X/W into 2x s8 planes (quad-permuted). One float4 per thread.
// ---------------------------------------------------------------------------
#define XQN (3 * MTOT * XWQ)  /* 3145728 quads */
#define WQN (3 * NTOT * XWQ)  /* 786432 quads */
#define PREP_BLOCKS ((XQN + WQN) / 256)  /* 15360 */

__global__ __launch_bounds__(256) void prep_quant(
    const float* __restrict__ xq, const float* __restrict__ xk, const float* __restrict__ xv,
    const float* __restrict__ wq, const float* __restrict__ wk, const float* __restrict__ wv)
{
    const int idx = blockIdx.x * 256 + threadIdx.x;
    const float* src;
    uint32_t *dA, *dB;
    int q;
    float LIM;
    if (idx < XQN) {
        const int z = idx / (MTOT * XWQ);
        const int r = idx - z * (MTOT * XWQ);
        const int row = r >> 8; q = r & 255;
        src = ((z == 0) ? xq : (z == 1) ? xk : xv) + (size_t)row * D_IN;
        dA = g_Xa + (size_t)z * MTOT * XWQ + (size_t)row * XWQ;
        dB = g_Xb + (size_t)z * MTOT * XWQ + (size_t)row * XWQ;
        LIM = LIMX;
    } else {
        const int r2 = idx - XQN;
        const int z = r2 / (NTOT * XWQ);
        const int r = r2 - z * (NTOT * XWQ);
        const int row = r >> 8; q = r & 255;
        src = ((z == 0) ? wq : (z == 1) ? wk : wv) + (size_t)row * D_IN;
        dA = g_Wa + (size_t)z * NTOT * XWQ + (size_t)row * XWQ;
        dB = g_Wb + (size_t)z * NTOT * XWQ + (size_t)row * XWQ;
        LIM = LIMW;
    }
    const float S = QMAX / LIM;
    float4 v = *(const float4*)(src + 4 * q);
    int i0 = __float2int_rn(fminf(fmaxf(v.x, -LIM), LIM) * S);
    int i1 = __float2int_rn(fminf(fmaxf(v.y, -LIM), LIM) * S);
    int i2 = __float2int_rn(fminf(fmaxf(v.z, -LIM), LIM) * S);
    int i3 = __float2int_rn(fminf(fmaxf(v.w, -LIM), LIM) * S);
    int a0 = (i0 + 128) >> 8, a1 = (i1 + 128) >> 8, a2 = (i2 + 128) >> 8, a3 = (i3 + 128) >> 8;
    int b0 = i0 - (a0 << 8), b1 = i1 - (a1 << 8), b2 = i2 - (a2 << 8), b3 = i3 - (a3 << 8);
    uint32_t pa = (uint32_t)(uint8_t)a0 | ((uint32_t)(uint8_t)a1 << 8) |
                  ((uint32_t)(uint8_t)a2 << 16) | ((uint32_t)(uint8_t)a3 << 24);
    uint32_t pb = (uint32_t)(uint8_t)b0 | ((uint32_t)(uint8_t)b1 << 8) |
                  ((uint32_t)(uint8_t)b2 << 16) | ((uint32_t)(uint8_t)b3 << 24);
    const int w = (q & ~7) + permpos(q & 7);
    dA[w] = pa;
    dB[w] = pb;
}

// ---------------------------------------------------------------------------
// Fused QKV GEMM, s8 16-bit fixed point (4 exact streams), m16n8k32.
// Block 64m x 128n, 16 warps (warp 16m x 32n), k-chunk 64 bytes, double-buffered.
// Row stride 24 words (16 data + 8 pad).
// ---------------------------------------------------------------------------
#define GS 24
#define O_XA 0                       /* 64*24 per buf; 2 bufs -> 3072 */
#define O_XB 3072
#define O_WA 6144                    /* 128*24 per buf; 2 bufs -> 6144 */
#define O_WB 12288
#define G8_SMEM_WORDS 18432
#define G8_SMEM_BYTES (G8_SMEM_WORDS * 4)   /* 73728 */
#define TS_LD 130

__global__ __launch_bounds__(512, 1) void qkv_gemm_s8(
    const float* __restrict__ bq, const float* __restrict__ bk, const float* __restrict__ bv)
{
    extern __shared__ uint32_t smw[];
    const int z = blockIdx.z;
    const float* bias = (z == 0) ? bq : (z == 1) ? bk : bv;

    const int tid = threadIdx.x;
    const int wid = tid >> 5, lane = tid & 31;
    const int g = lane >> 2, t = lane & 3;
    const int bm = blockIdx.y * 64;
    const int bn = blockIdx.x * 128;
    const int wm = (wid >> 2) * 16;
    const int wn = (wid & 3) * 32;
    const uint32_t smBase = (uint32_t)__cvta_generic_to_shared(smw);

    const uint32_t* SXa = g_Xa + (size_t)z * MTOT * XWQ + (size_t)bm * XWQ;
    const uint32_t* SXb = g_Xb + (size_t)z * MTOT * XWQ + (size_t)bm * XWQ;
    const uint32_t* SWa = g_Wa + (size_t)z * NTOT * XWQ + (size_t)bn * XWQ;
    const uint32_t* SWb = g_Wb + (size_t)z * NTOT * XWQ + (size_t)bn * XWQ;

#define G8_ISSUE(KC) do {                                                        \
    const int _buf = (KC) & 1;                                                   \
    _Pragma("unroll")                                                            \
    for (int _i = 0; _i < 3; _i++) {                                             \
        const int _u = tid + 512 * _i;                                           \
        if (_u < 512) {                                                          \
            const int _pl = _u >> 8;                                             \
            const int _v = _u & 255;                                             \
            const int _row = _v >> 2, _c = _v & 3;                               \
            const uint32_t* _s = (_pl ? SXb : SXa) + (size_t)_row * XWQ + (KC) * 16 + _c * 4; \
            cp_async16(smBase + ((_pl ? O_XB : O_XA) + _buf * 1536 +             \
                                 _row * GS + _c * 4) * 4, _s);                   \
        } else {                                                                 \
            const int _u2 = _u - 512;                                            \
            const int _pl = _u2 >> 9;                                            \
            const int _v = _u2 & 511;                                            \
            const int _row = _v >> 2, _c = _v & 3;                               \
            const uint32_t* _s = (_pl ? SWb : SWa) + (size_t)_row * XWQ + (KC) * 16 + _c * 4; \
            cp_async16(smBase + ((_pl ? O_WB : O_WA) + _buf * 3072 +             \
                                 _row * GS + _c * 4) * 4, _s);                   \
        }                                                                        \
    }                                                                            \
    cp_commit();                                                                 \
} while (0)

    int P1[4][4], P2[4][4], P3[4][4];
#pragma unroll
    for (int j = 0; j < 4; j++)
#pragma unroll
        for (int c = 0; c < 4; c++) { P1[j][c] = 0; P2[j][c] = 0; P3[j][c] = 0; }

    G8_ISSUE(0);
    G8_ISSUE(1);

    const int NKC = D_IN / 64;  // 16
    for (int kc = 0; kc < NKC; kc++) {
        if (kc == NKC - 1) cp_wait<0>(); else cp_wait<1>();
        __syncthreads();
        const int buf = kc & 1;
        const uint32_t* Axa = smw + O_XA + buf * 1536;
        const uint32_t* Axb = smw + O_XB + buf * 1536;
        const uint32_t* Bwa = smw + O_WA + buf * 3072;
        const uint32_t* Bwb = smw + O_WB + buf * 3072;
#pragma unroll
        for (int ks = 0; ks < 2; ks++) {
            uint32_t fa[4], fb[4];
            {
                const uint32_t* p = Axa + (wm + g) * GS + ks * 8 + 2 * t;
                uint2 x0 = *(const uint2*)p;
                uint2 x1 = *(const uint2*)(p + 8 * GS);
                fa[0] = x0.x; fa[1] = x1.x; fa[2] = x0.y; fa[3] = x1.y;
                const uint32_t* q = Axb + (wm + g) * GS + ks * 8 + 2 * t;
                uint2 y0 = *(const uint2*)q;
                uint2 y1 = *(const uint2*)(q + 8 * GS);
                fb[0] = y0.x; fb[1] = y1.x; fb[2] = y0.y; fb[3] = y1.y;
            }
#pragma unroll
            for (int j = 0; j < 4; j++) {
                const int col = wn + j * 8 + g;
                uint2 ba = *(const uint2*)(Bwa + col * GS + ks * 8 + 2 * t);
                uint2 bb = *(const uint2*)(Bwb + col * GS + ks * 8 + 2 * t);
                mma_s8(P1[j], fa, ba);
                mma_s8(P2[j], fa, bb);
                mma_s8(P2[j], fb, ba);
                mma_s8(P3[j], fb, bb);
            }
        }
        __syncthreads();
        if (kc + 2 < NKC) G8_ISSUE(kc + 2);
    }

    const float inv = (LIMX * LIMW) / (QMAX * QMAX);

    if (z < 2) {
        uint32_t* PH = (z == 0) ? g_Qh : g_Kh;
        uint32_t* PL = (z == 0) ? g_Ql : g_Kl;
        const float scale = (z == 0) ? 0.125f : 1.0f;
        const int head = (bn >> 6) + ((wn >= 64) ? 1 : 0);
#pragma unroll
        for (int half = 0; half < 2; half++) {
            const int m = bm + wm + half * 8 + g;
            const int b = m >> 11;
            const int s = m & (SEQ - 1);
            const size_t base = ((size_t)(b * NHEAD + head) * SEQ + s) * DPAIRS;
#pragma unroll
            for (int j = 0; j < 4; j++) {
                const int col = bn + wn + j * 8 + 2 * t;
                const float f0 = (fmaf(65536.f, (float)P1[j][half * 2],
                                  fmaf(256.f, (float)P2[j][half * 2],
                                       (float)P3[j][half * 2])) * inv + bias[col]) * scale;
                const float f1 = (fmaf(65536.f, (float)P1[j][half * 2 + 1],
                                  fmaf(256.f, (float)P2[j][half * 2 + 1],
                                       (float)P3[j][half * 2 + 1])) * inv + bias[col + 1]) * scale;
                uint32_t hw, lw;
                split_h(f0, f1, hw, lw);
                const int p = ((wn & 63) >> 1) + 4 * j + t;
                const int word = (p & ~7) + permpos(p & 7);
                PH[base + word] = hw;
                PL[base + word] = lw;
            }
        }
    } else {
        // V: stage fp32 tile to smem, transpose, store fp16 hi plane.
        float* Ts = (float*)smw;
        __syncthreads();
#pragma unroll
        for (int half = 0; half < 2; half++) {
            const int row = wm + half * 8 + g;
#pragma unroll
            for (int j = 0; j < 4; j++) {
                const int col = wn + j * 8 + 2 * t;
                Ts[row * TS_LD + col] =
                    fmaf(65536.f, (float)P1[j][half * 2],
                         fmaf(256.f, (float)P2[j][half * 2], (float)P3[j][half * 2])) * inv
                    + bias[bn + col];
                Ts[row * TS_LD + col + 1] =
                    fmaf(65536.f, (float)P1[j][half * 2 + 1],
                         fmaf(256.f, (float)P2[j][half * 2 + 1], (float)P3[j][half * 2 + 1])) * inv
                    + bias[bn + col + 1];
            }
        }
        __syncthreads();
        const int b = bm >> 11;
        const int sloc = bm & (SEQ - 1);
#pragma unroll
        for (int i = 0; i < 8; i++) {
            const int linear = i * 512 + tid;   // 4096 pair-elements (32 sp x 128 d)
            const int dloc = linear >> 5;       // 0..127
            const int sp = linear & 31;
            const float v0 = Ts[(2 * sp) * TS_LD + dloc];
            const float v1 = Ts[(2 * sp + 1) * TS_LD + dloc];
            const int dg = bn + dloc;
            const int h = dg >> 6, dh = dg & 63;
            const int aps = (sloc >> 1) + sp;
            const int word = (aps & ~7) + permpos(aps & 7);
            g_VTh[((size_t)(b * NHEAD + h) * NHID + dh) * SPAIRS + word] = f2h2(v0, v1);
        }
    }
#undef G8_ISSUE
}

// ---------------------------------------------------------------------------
// Flash attention, fp16 (verbatim R7). BQ=128, BKV=64, 8 warps (16q x 64kv),
// 2 CTAs/SM. QK 3-term; PV 1-term. Row stride 40 words.
// ---------------------------------------------------------------------------
#define A_STRIDE 40
#define QW (128 * A_STRIDE)
#define KVW (64 * A_STRIDE)
#define O_QH 0
#define O_QL QW
#define O_KH (2 * QW)
#define O_KL (2 * QW + 2 * KVW)
#define O_VH (2 * QW + 4 * KVW)
#define ATT_SMEM_WORDS (2 * QW + 6 * KVW)
#define ATT_SMEM_BYTES (ATT_SMEM_WORDS * 4) /* 102400 */

__device__ __forceinline__ void attn_stage_kv(const uint32_t* Kh, const uint32_t* Kl,
                                              const uint32_t* Vh,
                                              uint32_t smBase, int tid, int it) {
    const int buf = it & 1;
    const int kv0 = it * 64;
#pragma unroll
    for (int i = 0; i < 2; i++) {
        const int row = i * 32 + (tid >> 3);
        const int off = (tid & 7) * 4;
        const uint32_t d = smBase + (buf * KVW + row * A_STRIDE + off) * 4;
        cp_async16(d + O_KH * 4, Kh + (size_t)(kv0 + row) * DPAIRS + off);
        cp_async16(d + O_KL * 4, Kl + (size_t)(kv0 + row) * DPAIRS + off);
        cp_async16(d + O_VH * 4, Vh + (size_t)row * SPAIRS + it * DPAIRS + off);
    }
    cp_commit();
}

__global__ __launch_bounds__(256, 2) void attn_fp16(float* __restrict__ out)
{
    extern __shared__ uint32_t smw[];

    const int tid = threadIdx.x;
    const int warp = tid >> 5, lane = tid & 31;
    const int g = lane >> 2, t = lane & 3;
    const int bh = blockIdx.y;
    const int q0 = blockIdx.x * 128;
    const int wq = warp * 16;

    const uint32_t* Qh = g_Qh + ((size_t)bh * SEQ + q0) * DPAIRS;
    const uint32_t* Ql = g_Ql + ((size_t)bh * SEQ + q0) * DPAIRS;
    const uint32_t* Kh = g_Kh + (size_t)bh * SEQ * DPAIRS;
    const uint32_t* Kl = g_Kl + (size_t)bh * SEQ * DPAIRS;
    const uint32_t* Vh = g_VTh + (size_t)bh * NHID * SPAIRS;

    const uint32_t smBase = (uint32_t)__cvta_generic_to_shared(smw);

#pragma unroll
    for (int i = 0; i < 4; i++) {
        const int c = tid + 256 * i;
        const int row = c >> 3;
        const int off = (c & 7) * 4;
        cp_async16(smBase + (O_QH + row * A_STRIDE + off) * 4, Qh + (size_t)row * DPAIRS + off);
        cp_async16(smBase + (O_QL + row * A_STRIDE + off) * 4, Ql + (size_t)row * DPAIRS + off);
    }
    attn_stage_kv(Kh, Kl, Vh, smBase, tid, 0);
    attn_stage_kv(Kh, Kl, Vh, smBase, tid, 1);

    float m_i[2], l_i[2], O[8][4];
#pragma unroll
    for (int r = 0; r < 2; r++) { m_i[r] = -INFINITY; l_i[r] = 0.0f; }
#pragma unroll
    for (int j = 0; j < 8; j++)
#pragma unroll
        for (int c = 0; c < 4; c++) O[j][c] = 0.0f;

    const int NIT = SEQ / 64;  // 32
    for (int it = 0; it < NIT; it++) {
        if (it == NIT - 1) cp_wait<0>(); else cp_wait<1>();
        __syncthreads();
        const int buf = it & 1;
        const uint32_t* Khb = smw + O_KH + buf * KVW;
        const uint32_t* Klb = smw + O_KL + buf * KVW;
        const uint32_t* Vhb = smw + O_VH + buf * KVW;

        float S[8][4];
#pragma unroll
        for (int j = 0; j < 8; j++)
#pragma unroll
            for (int c = 0; c < 4; c++) S[j][c] = 0.0f;

#pragma unroll
        for (int ks = 0; ks < 4; ks++) {
            uint32_t qh[4], ql[4];
            {
                const uint32_t* p = smw + O_QH + (wq + g) * A_STRIDE + ks * 8 + 2 * t;
                uint2 x0 = *(const uint2*)p;
                uint2 x1 = *(const uint2*)(p + 8 * A_STRIDE);
                qh[0] = x0.x; qh[1] = x1.x; qh[2] = x0.y; qh[3] = x1.y;
                const uint32_t* q = smw + O_QL + (wq + g) * A_STRIDE + ks * 8 + 2 * t;
                uint2 y0 = *(const uint2*)q;
                uint2 y1 = *(const uint2*)(q + 8 * A_STRIDE);
                ql[0] = y0.x; ql[1] = y1.x; ql[2] = y0.y; ql[3] = y1.y;
            }
#pragma unroll
            for (int j = 0; j < 8; j++) {
                uint2 kh = *(const uint2*)(Khb + (j * 8 + g) * A_STRIDE + ks * 8 + 2 * t);
                uint2 kl = *(const uint2*)(Klb + (j * 8 + g) * A_STRIDE + ks * 8 + 2 * t);
                mma_fp16(S[j], qh, kh);
                mma_fp16(S[j], ql, kh);
                mma_fp16(S[j], qh, kl);
            }
        }

#pragma unroll
        for (int half = 0; half < 2; half++) {
            float mx = -INFINITY;
#pragma unroll
            for (int j = 0; j < 8; j++)
                mx = fmaxf(mx, fmaxf(S[j][half * 2], S[j][half * 2 + 1]));
            mx = fmaxf(mx, __shfl_xor_sync(0xffffffffu, mx, 1));
            mx = fmaxf(mx, __shfl_xor_sync(0xffffffffu, mx, 2));
            const float mn = fmaxf(m_i[half], mx);
            const float corr = __expf(m_i[half] - mn);
            m_i[half] = mn;
            float rs = 0.0f;
#pragma unroll
            for (int j = 0; j < 8; j++) {
                const float e0 = __expf(S[j][half * 2]     - mn);
                const float e1 = __expf(S[j][half * 2 + 1] - mn);
                S[j][half * 2]     = e0;
                S[j][half * 2 + 1] = e1;
                rs += e0 + e1;
            }
            rs += __shfl_xor_sync(0xffffffffu, rs, 1);
            rs += __shfl_xor_sync(0xffffffffu, rs, 2);
            l_i[half] = l_i[half] * corr + rs;
#pragma unroll
            for (int j = 0; j < 8; j++) {
                O[j][half * 2]     *= corr;
                O[j][half * 2 + 1] *= corr;
            }
        }

#pragma unroll
        for (int ks = 0; ks < 4; ks++) {
            uint32_t pf[4];
            pf[0] = f2h2(S[2 * ks][0],     S[2 * ks][1]);
            pf[1] = f2h2(S[2 * ks][2],     S[2 * ks][3]);
            pf[2] = f2h2(S[2 * ks + 1][0], S[2 * ks + 1][1]);
            pf[3] = f2h2(S[2 * ks + 1][2], S[2 * ks + 1][3]);
#pragma unroll
            for (int j = 0; j < 8; j++) {
                uint2 vh = *(const uint2*)(Vhb + (j * 8 + g) * A_STRIDE + ks * 8 + 2 * t);
                mma_fp16(O[j], pf, vh);
            }
        }

        __syncthreads();
        if (it + 2 < NIT) attn_stage_kv(Kh, Kl, Vh, smBase, tid, it + 2);
    }

    const int b = bh >> 4, h = bh & 15;
#pragma unroll
    for (int half = 0; half < 2; half++) {
        const float inv = 1.0f / l_i[half];
        const int q = q0 + wq + half * 8 + g;
        float* orow = out + (size_t)(b * SEQ + q) * NTOT + h * NHID;
#pragma unroll
        for (int j = 0; j < 8; j++) {
            float2 v = make_float2(O[j][half * 2] * inv, O[j][half * 2 + 1] * inv);
            *(float2*)(orow + j * 8 + 2 * t) = v;
        }
    }
}

// ---------------------------------------------------------------------------
extern "C" void kernel_launch(void* const* d_in, const int* in_sizes, int n_in,
                              void* d_out, int out_size)
{
    const float* xq = (const float*)d_in[0];
    const float* xk = (const float*)d_in[1];
    const float* xv = (const float*)d_in[2];
    const float* wq = (const float*)d_in[3];
    const float* bq = (const float*)d_in[4];
    const float* wk = (const float*)d_in[5];
    const float* bk = (const float*)d_in[6];
    const float* wv = (const float*)d_in[7];
    const float* bv = (const float*)d_in[8];
    float* out = (float*)d_out;

    cudaFuncSetAttribute(qkv_gemm_s8, cudaFuncAttributeMaxDynamicSharedMemorySize,
                         G8_SMEM_BYTES);
    cudaFuncSetAttribute(attn_fp16, cudaFuncAttributeMaxDynamicSharedMemorySize,
                         ATT_SMEM_BYTES);

    prep_quant<<<PREP_BLOCKS, 256>>>(xq, xk, xv, wq, wk, wv);

    dim3 gg(NTOT / 128, MTOT / 64, 3);
    qkv_gemm_s8<<<gg, 512, G8_SMEM_BYTES>>>(bq, bk, bv);

    dim3 ga(SEQ / 128, BH);
    attn_fp16<<<ga, 256, ATT_SMEM_BYTES>>>(out);
}

// round 14
// speedup vs baseline: 1.3662x; 1.0793x over previous
#include <cuda_runtime.h>
#include <cuda_fp16.h>
#include <math.h>
#include <stdint.h>

#define D_IN 1024
#define NHEAD 16
#define NHID 64
#define BATCH 2
#define SEQ 2048
#define MTOT (BATCH * SEQ)   /* 4096 */
#define NTOT (NHEAD * NHID)  /* 1024 */
#define BH (BATCH * NHEAD)   /* 32 */
#define DPAIRS (NHID / 2)    /* 32 */
#define SPAIRS (SEQ / 2)     /* 1024 */
#define XWQ 256              /* quad-words per row of X/W s8 planes */
#define QKW 16               /* quad-words per row of Q/K s8 planes */

// Quantization: value = (a*256 + b) / (QMAX/LIM).
#define LIMX 6.0f
#define LIMW 0.26f
#define LIMQ 1.5f
#define LIMK 9.0f
#define QMAX 32511.0f

// s8 planes, quad-permuted [w0,w4,w1,w5,w2,w6,w3,w7] per 8-word (32 B) group.
__device__ uint32_t g_Xa[(size_t)3 * MTOT * XWQ];
__device__ uint32_t g_Xb[(size_t)3 * MTOT * XWQ];
__device__ uint32_t g_Wa[(size_t)3 * NTOT * XWQ];
__device__ uint32_t g_Wb[(size_t)3 * NTOT * XWQ];
// Q/K: (B,H,S, 16 words) s8 split planes, permuted (Q pre-scaled by 0.125).
__device__ uint32_t g_Qa[(size_t)BH * SEQ * QKW];
__device__ uint32_t g_Qb[(size_t)BH * SEQ * QKW];
__device__ uint32_t g_Ka[(size_t)BH * SEQ * QKW];
__device__ uint32_t g_Kb[(size_t)BH * SEQ * QKW];
// V: (B,H,Dh,S-pairs) fp16 hi plane, pair-permuted (unchanged from R13).
__device__ uint32_t g_VTh[(size_t)BH * NHID * SPAIRS];

// ---------------------------------------------------------------------------
__device__ __forceinline__ int permpos(int p) { return p < 4 ? 2 * p : 2 * p - 7; }
__device__ __forceinline__ int invperm(int p) { return (p & 1) ? (p + 7) >> 1 : p >> 1; }

__device__ __forceinline__ uint32_t f2h2(float a, float b) {
    __half2 h = __float22half2_rn(make_float2(a, b));
    return *reinterpret_cast<uint32_t*>(&h);
}
__device__ __forceinline__ void quant16(float v, float S, float LIM, int& a, int& b) {
    int i = __float2int_rn(fminf(fmaxf(v, -LIM), LIM) * S);
    a = (i + 128) >> 8;
    b = i - (a << 8);
}
__device__ __forceinline__ void mma_fp16(float* d, const uint32_t* a, uint2 b) {
    asm volatile(
        "mma.sync.aligned.m16n8k16.row.col.f32.f16.f16.f32 "
        "{%0,%1,%2,%3}, {%4,%5,%6,%7}, {%8,%9}, {%0,%1,%2,%3};\n"
        : "+f"(d[0]), "+f"(d[1]), "+f"(d[2]), "+f"(d[3])
        : "r"(a[0]), "r"(a[1]), "r"(a[2]), "r"(a[3]), "r"(b.x), "r"(b.y));
}
__device__ __forceinline__ void mma_s8(int* d, const uint32_t* a, uint2 b) {
    asm volatile(
        "mma.sync.aligned.m16n8k32.row.col.s32.s8.s8.s32 "
        "{%0,%1,%2,%3}, {%4,%5,%6,%7}, {%8,%9}, {%0,%1,%2,%3};\n"
        : "+r"(d[0]), "+r"(d[1]), "+r"(d[2]), "+r"(d[3])
        : "r"(a[0]), "r"(a[1]), "r"(a[2]), "r"(a[3]), "r"(b.x), "r"(b.y));
}
__device__ __forceinline__ void cp_async16(uint32_t dst, const void* src) {
    asm volatile("cp.async.cg.shared.global [%0], [%1], 16;\n" :: "r"(dst), "l"(src));
}
__device__ __forceinline__ void cp_commit() { asm volatile("cp.async.commit_group;\n"); }
template <int N>
__device__ __forceinline__ void cp_wait() { asm volatile("cp.async.wait_group %0;\n" :: "n"(N)); }

// ---------------------------------------------------------------------------
// Prep: quantize X/W into 2x s8 planes (quad-permuted). One float4 per thread.
// ---------------------------------------------------------------------------
#define XQN (3 * MTOT * XWQ)
#define WQN (3 * NTOT * XWQ)
#define PREP_BLOCKS ((XQN + WQN) / 256)

__global__ __launch_bounds__(256) void prep_quant(
    const float* __restrict__ xq, const float* __restrict__ xk, const float* __restrict__ xv,
    const float* __restrict__ wq, const float* __restrict__ wk, const float* __restrict__ wv)
{
    const int idx = blockIdx.x * 256 + threadIdx.x;
    const float* src;
    uint32_t *dA, *dB;
    int q;
    float LIM;
    if (idx < XQN) {
        const int z = idx / (MTOT * XWQ);
        const int r = idx - z * (MTOT * XWQ);
        const int row = r >> 8; q = r & 255;
        src = ((z == 0) ? xq : (z == 1) ? xk : xv) + (size_t)row * D_IN;
        dA = g_Xa + (size_t)z * MTOT * XWQ + (size_t)row * XWQ;
        dB = g_Xb + (size_t)z * MTOT * XWQ + (size_t)row * XWQ;
        LIM = LIMX;
    } else {
        const int r2 = idx - XQN;
        const int z = r2 / (NTOT * XWQ);
        const int r = r2 - z * (NTOT * XWQ);
        const int row = r >> 8; q = r & 255;
        src = ((z == 0) ? wq : (z == 1) ? wk : wv) + (size_t)row * D_IN;
        dA = g_Wa + (size_t)z * NTOT * XWQ + (size_t)row * XWQ;
        dB = g_Wb + (size_t)z * NTOT * XWQ + (size_t)row * XWQ;
        LIM = LIMW;
    }
    const float S = QMAX / LIM;
    float4 v = *(const float4*)(src + 4 * q);
    int a0, b0, a1, b1, a2, b2, a3, b3;
    quant16(v.x, S, LIM, a0, b0);
    quant16(v.y, S, LIM, a1, b1);
    quant16(v.z, S, LIM, a2, b2);
    quant16(v.w, S, LIM, a3, b3);
    uint32_t pa = (uint32_t)(uint8_t)a0 | ((uint32_t)(uint8_t)a1 << 8) |
                  ((uint32_t)(uint8_t)a2 << 16) | ((uint32_t)(uint8_t)a3 << 24);
    uint32_t pb = (uint32_t)(uint8_t)b0 | ((uint32_t)(uint8_t)b1 << 8) |
                  ((uint32_t)(uint8_t)b2 << 16) | ((uint32_t)(uint8_t)b3 << 24);
    const int w = (q & ~7) + permpos(q & 7);
    dA[w] = pa;
    dB[w] = pb;
}

// ---------------------------------------------------------------------------
// Fused QKV GEMM, s8 16-bit fixed point (4 exact streams), m16n8k32.
// Block 64m x 128n, 16 warps (warp 16m x 32n). Epilogue: Q/K -> s8 planes,
// V -> fp16 transposed plane.
// ---------------------------------------------------------------------------
#define GS 24
#define O_XA 0
#define O_XB 3072
#define O_WA 6144
#define O_WB 12288
#define G8_SMEM_WORDS 18432
#define G8_SMEM_BYTES (G8_SMEM_WORDS * 4)   /* 73728 */
#define TS_LD 130

__global__ __launch_bounds__(512, 1) void qkv_gemm_s8(
    const float* __restrict__ bq, const float* __restrict__ bk, const float* __restrict__ bv)
{
    extern __shared__ uint32_t smw[];
    const int z = blockIdx.z;
    const float* bias = (z == 0) ? bq : (z == 1) ? bk : bv;

    const int tid = threadIdx.x;
    const int wid = tid >> 5, lane = tid & 31;
    const int g = lane >> 2, t = lane & 3;
    const int bm = blockIdx.y * 64;
    const int bn = blockIdx.x * 128;
    const int wm = (wid >> 2) * 16;
    const int wn = (wid & 3) * 32;
    const uint32_t smBase = (uint32_t)__cvta_generic_to_shared(smw);

    const uint32_t* SXa = g_Xa + (size_t)z * MTOT * XWQ + (size_t)bm * XWQ;
    const uint32_t* SXb = g_Xb + (size_t)z * MTOT * XWQ + (size_t)bm * XWQ;
    const uint32_t* SWa = g_Wa + (size_t)z * NTOT * XWQ + (size_t)bn * XWQ;
    const uint32_t* SWb = g_Wb + (size_t)z * NTOT * XWQ + (size_t)bn * XWQ;

#define G8_ISSUE(KC) do {                                                        \
    const int _buf = (KC) & 1;                                                   \
    _Pragma("unroll")                                                            \
    for (int _i = 0; _i < 3; _i++) {                                             \
        const int _u = tid + 512 * _i;                                           \
        if (_u < 512) {                                                          \
            const int _pl = _u >> 8;                                             \
            const int _v = _u & 255;                                             \
            const int _row = _v >> 2, _c = _v & 3;                               \
            const uint32_t* _s = (_pl ? SXb : SXa) + (size_t)_row * XWQ + (KC) * 16 + _c * 4; \
            cp_async16(smBase + ((_pl ? O_XB : O_XA) + _buf * 1536 +             \
                                 _row * GS + _c * 4) * 4, _s);                   \
        } else {                                                                 \
            const int _u2 = _u - 512;                                            \
            const int _pl = _u2 >> 9;                                            \
            const int _v = _u2 & 511;                                            \
            const int _row = _v >> 2, _c = _v & 3;                               \
            const uint32_t* _s = (_pl ? SWb : SWa) + (size_t)_row * XWQ + (KC) * 16 + _c * 4; \
            cp_async16(smBase + ((_pl ? O_WB : O_WA) + _buf * 3072 +             \
                                 _row * GS + _c * 4) * 4, _s);                   \
        }                                                                        \
    }                                                                            \
    cp_commit();                                                                 \
} while (0)

    int P1[4][4], P2[4][4], P3[4][4];
#pragma unroll
    for (int j = 0; j < 4; j++)
#pragma unroll
        for (int c = 0; c < 4; c++) { P1[j][c] = 0; P2[j][c] = 0; P3[j][c] = 0; }

    G8_ISSUE(0);
    G8_ISSUE(1);

    const int NKC = D_IN / 64;  // 16
    for (int kc = 0; kc < NKC; kc++) {
        if (kc == NKC - 1) cp_wait<0>(); else cp_wait<1>();
        __syncthreads();
        const int buf = kc & 1;
        const uint32_t* Axa = smw + O_XA + buf * 1536;
        const uint32_t* Axb = smw + O_XB + buf * 1536;
        const uint32_t* Bwa = smw + O_WA + buf * 3072;
        const uint32_t* Bwb = smw + O_WB + buf * 3072;
#pragma unroll
        for (int ks = 0; ks < 2; ks++) {
            uint32_t fa[4], fb[4];
            {
                const uint32_t* p = Axa + (wm + g) * GS + ks * 8 + 2 * t;
                uint2 x0 = *(const uint2*)p;
                uint2 x1 = *(const uint2*)(p + 8 * GS);
                fa[0] = x0.x; fa[1] = x1.x; fa[2] = x0.y; fa[3] = x1.y;
                const uint32_t* q = Axb + (wm + g) * GS + ks * 8 + 2 * t;
                uint2 y0 = *(const uint2*)q;
                uint2 y1 = *(const uint2*)(q + 8 * GS);
                fb[0] = y0.x; fb[1] = y1.x; fb[2] = y0.y; fb[3] = y1.y;
            }
#pragma unroll
            for (int j = 0; j < 4; j++) {
                const int col = wn + j * 8 + g;
                uint2 ba = *(const uint2*)(Bwa + col * GS + ks * 8 + 2 * t);
                uint2 bb = *(const uint2*)(Bwb + col * GS + ks * 8 + 2 * t);
                mma_s8(P1[j], fa, ba);
                mma_s8(P2[j], fa, bb);
                mma_s8(P2[j], fb, ba);
                mma_s8(P3[j], fb, bb);
            }
        }
        __syncthreads();
        if (kc + 2 < NKC) G8_ISSUE(kc + 2);
    }

    const float inv = (LIMX * LIMW) / (QMAX * QMAX);
    const float scale = (z == 0) ? 0.125f : 1.0f;

    // Stage de-scaled fp32 tile (with bias and Q pre-scale) to smem.
    float* Ts = (float*)smw;
    __syncthreads();
#pragma unroll
    for (int half = 0; half < 2; half++) {
        const int row = wm + half * 8 + g;
#pragma unroll
        for (int j = 0; j < 4; j++) {
            const int col = wn + j * 8 + 2 * t;
            const float f0 =
                (fmaf(65536.f, (float)P1[j][half * 2],
                      fmaf(256.f, (float)P2[j][half * 2], (float)P3[j][half * 2])) * inv
                 + bias[bn + col]) * scale;
            const float f1 =
                (fmaf(65536.f, (float)P1[j][half * 2 + 1],
                      fmaf(256.f, (float)P2[j][half * 2 + 1], (float)P3[j][half * 2 + 1])) * inv
                 + bias[bn + col + 1]) * scale;
            Ts[row * TS_LD + col]     = f0;
            Ts[row * TS_LD + col + 1] = f1;
        }
    }
    __syncthreads();

    const int b = bm >> 11;
    if (z < 2) {
        // Quantize Q/K rows to s8 split planes (16 words/row, permuted).
        uint32_t* PA = (z == 0) ? g_Qa : g_Ka;
        uint32_t* PB = (z == 0) ? g_Qb : g_Kb;
        const float LIM = (z == 0) ? LIMQ : LIMK;
        const float Sq = QMAX / LIM;
        const int head_base = bn >> 6;
        const int sloc = bm & (SEQ - 1);
#pragma unroll
        for (int i = 0; i < 4; i++) {
            const int lin = i * 512 + tid;      // 0..2047 (64 rows x 32 words)
            const int row = lin >> 5;
            const int wg = lin & 31;
            const int hl = wg >> 4;             // head within tile
            const int p = wg & 15;              // permuted word pos in row
            const int qw = invperm(p & 7) + (p & 8);   // original word
            const float* src = Ts + row * TS_LD + hl * 64 + 4 * qw;
            int a0, b0, a1, b1, a2, b2, a3, b3;
            quant16(src[0], Sq, LIM, a0, b0);
            quant16(src[1], Sq, LIM, a1, b1);
            quant16(src[2], Sq, LIM, a2, b2);
            quant16(src[3], Sq, LIM, a3, b3);
            uint32_t pa = (uint32_t)(uint8_t)a0 | ((uint32_t)(uint8_t)a1 << 8) |
                          ((uint32_t)(uint8_t)a2 << 16) | ((uint32_t)(uint8_t)a3 << 24);
            uint32_t pb = (uint32_t)(uint8_t)b0 | ((uint32_t)(uint8_t)b1 << 8) |
                          ((uint32_t)(uint8_t)b2 << 16) | ((uint32_t)(uint8_t)b3 << 24);
            const size_t base =
                ((size_t)(b * NHEAD + head_base + hl) * SEQ + (sloc + row)) * QKW;
            PA[base + p] = pa;
            PB[base + p] = pb;
        }
    } else {
        // V: transpose, store fp16 hi plane (B,H,Dh,S-pairs).
        const int sloc = bm & (SEQ - 1);
#pragma unroll
        for (int i = 0; i < 8; i++) {
            const int linear = i * 512 + tid;   // 4096 pair-elements
            const int dloc = linear >> 5;       // 0..127
            const int sp = linear & 31;
            const float v0 = Ts[(2 * sp) * TS_LD + dloc];
            const float v1 = Ts[(2 * sp + 1) * TS_LD + dloc];
            const int dg = bn + dloc;
            const int h = dg >> 6, dh = dg & 63;
            const int aps = (sloc >> 1) + sp;
            const int word = (aps & ~7) + permpos(aps & 7);
            g_VTh[((size_t)(b * NHEAD + h) * NHID + dh) * SPAIRS + word] = f2h2(v0, v1);
        }
    }
#undef G8_ISSUE
}

// ---------------------------------------------------------------------------
// Flash attention: QK on s8 (3-stream 16-bit fixed point, m16n8k32),
// softmax fp32, PV fp16 1-term. BQ=128, BKV=64, 8 warps (16q x 64kv), 2 CTA/SM.
// ---------------------------------------------------------------------------
#define KS8 24                    /* Q/K row stride (16 data + 8 pad) */
#define VSW 40                    /* V row stride */
#define O_QA 0                    /* 128*24 = 3072 */
#define O_QB 3072
#define O_KA 6144                 /* 2 bufs x 64*24 = 3072 */
#define O_KB 9216
#define O_VH 12288                /* 2 bufs x 64*40 = 5120 */
#define ATT_SMEM_WORDS 17408
#define ATT_SMEM_BYTES (ATT_SMEM_WORDS * 4)  /* 69632 */
#define DSC ((LIMQ * LIMK) / (QMAX * QMAX))

__device__ __forceinline__ void attn_stage_kv(const uint32_t* Ka, const uint32_t* Kb,
                                              const uint32_t* Vh,
                                              uint32_t smBase, int tid, int it) {
    const int buf = it & 1;
    const int kv0 = it * 64;
#pragma unroll
    for (int i = 0; i < 2; i++) {
        const int c = tid + 256 * i;           // 0..511
        // K planes: 2 x 64 rows x 4 chunks
        const int pl = c >> 8;
        const int cc = c & 255;
        const int row = cc >> 2;
        const int off = (cc & 3) * 4;
        cp_async16(smBase + ((pl ? O_KB : O_KA) + buf * 1536 + row * KS8 + off) * 4,
                   (pl ? Kb : Ka) + (size_t)(kv0 + row) * QKW + off);
        // V: 64 dh-rows x 8 chunks
        const int row2 = c >> 3;
        const int off2 = (c & 7) * 4;
        cp_async16(smBase + (O_VH + buf * 2560 + row2 * VSW + off2) * 4,
                   Vh + (size_t)row2 * SPAIRS + it * 32 + off2);
    }
    cp_commit();
}

__global__ __launch_bounds__(256, 2) void attn_s8(float* __restrict__ out)
{
    extern __shared__ uint32_t smw[];

    const int tid = threadIdx.x;
    const int warp = tid >> 5, lane = tid & 31;
    const int g = lane >> 2, t = lane & 3;
    const int bh = blockIdx.y;
    const int q0 = blockIdx.x * 128;
    const int wq = warp * 16;

    const uint32_t* Qa = g_Qa + ((size_t)bh * SEQ + q0) * QKW;
    const uint32_t* Qb = g_Qb + ((size_t)bh * SEQ + q0) * QKW;
    const uint32_t* Ka = g_Ka + (size_t)bh * SEQ * QKW;
    const uint32_t* Kb = g_Kb + (size_t)bh * SEQ * QKW;
    const uint32_t* Vh = g_VTh + (size_t)bh * NHID * SPAIRS;

    const uint32_t smBase = (uint32_t)__cvta_generic_to_shared(smw);

    // Q tile: 2 planes x 128 rows x 4 chunks = 1024 chunks.
#pragma unroll
    for (int i = 0; i < 4; i++) {
        const int c = tid + 256 * i;            // 0..1023
        const int pl = c >> 9;
        const int cc = c & 511;
        const int row = cc >> 2;
        const int off = (cc & 3) * 4;
        cp_async16(smBase + ((pl ? O_QB : O_QA) + row * KS8 + off) * 4,
                   (pl ? Qb : Qa) + (size_t)row * QKW + off);
    }
    attn_stage_kv(Ka, Kb, Vh, smBase, tid, 0);
    attn_stage_kv(Ka, Kb, Vh, smBase, tid, 1);

    float m_i[2], l_i[2], O[8][4];
#pragma unroll
    for (int r = 0; r < 2; r++) { m_i[r] = -INFINITY; l_i[r] = 0.0f; }
#pragma unroll
    for (int j = 0; j < 8; j++)
#pragma unroll
        for (int c = 0; c < 4; c++) O[j][c] = 0.0f;

    const int NIT = SEQ / 64;  // 32
    for (int it = 0; it < NIT; it++) {
        if (it == NIT - 1) cp_wait<0>(); else cp_wait<1>();
        __syncthreads();
        const int buf = it & 1;
        const uint32_t* KAb = smw + O_KA + buf * 1536;
        const uint32_t* KBb = smw + O_KB + buf * 1536;
        const uint32_t* Vhb = smw + O_VH + buf * 2560;

        // ---- scores: 3-stream s8 IMMA (aa, ab, ba) ----
        int P1[8][4], P2[8][4];
#pragma unroll
        for (int j = 0; j < 8; j++)
#pragma unroll
            for (int c = 0; c < 4; c++) { P1[j][c] = 0; P2[j][c] = 0; }

#pragma unroll
        for (int ks = 0; ks < 2; ks++) {
            uint32_t fa[4], fb[4];
            {
                const uint32_t* p = smw + O_QA + (wq + g) * KS8 + ks * 8 + 2 * t;
                uint2 x0 = *(const uint2*)p;
                uint2 x1 = *(const uint2*)(p + 8 * KS8);
                fa[0] = x0.x; fa[1] = x1.x; fa[2] = x0.y; fa[3] = x1.y;
                const uint32_t* q = smw + O_QB + (wq + g) * KS8 + ks * 8 + 2 * t;
                uint2 y0 = *(const uint2*)q;
                uint2 y1 = *(const uint2*)(q + 8 * KS8);
                fb[0] = y0.x; fb[1] = y1.x; fb[2] = y0.y; fb[3] = y1.y;
            }
#pragma unroll
            for (int j = 0; j < 8; j++) {
                uint2 ba = *(const uint2*)(KAb + (j * 8 + g) * KS8 + ks * 8 + 2 * t);
                uint2 bb = *(const uint2*)(KBb + (j * 8 + g) * KS8 + ks * 8 + 2 * t);
                mma_s8(P1[j], fa, ba);
                mma_s8(P2[j], fa, bb);
                mma_s8(P2[j], fb, ba);
            }
        }

        float S[8][4];
#pragma unroll
        for (int j = 0; j < 8; j++)
#pragma unroll
            for (int c = 0; c < 4; c++)
                S[j][c] = (fmaf(65536.f, (float)P1[j][c], 256.f * (float)P2[j][c])) * DSC;

        // ---- online softmax ----
#pragma unroll
        for (int half = 0; half < 2; half++) {
            float mx = -INFINITY;
#pragma unroll
            for (int j = 0; j < 8; j++)
                mx = fmaxf(mx, fmaxf(S[j][half * 2], S[j][half * 2 + 1]));
            mx = fmaxf(mx, __shfl_xor_sync(0xffffffffu, mx, 1));
            mx = fmaxf(mx, __shfl_xor_sync(0xffffffffu, mx, 2));
            const float mn = fmaxf(m_i[half], mx);
            const float corr = __expf(m_i[half] - mn);
            m_i[half] = mn;
            float rs = 0.0f;
#pragma unroll
            for (int j = 0; j < 8; j++) {
                const float e0 = __expf(S[j][half * 2]     - mn);
                const float e1 = __expf(S[j][half * 2 + 1] - mn);
                S[j][half * 2]     = e0;
                S[j][half * 2 + 1] = e1;
                rs += e0 + e1;
            }
            rs += __shfl_xor_sync(0xffffffffu, rs, 1);
            rs += __shfl_xor_sync(0xffffffffu, rs, 2);
            l_i[half] = l_i[half] * corr + rs;
#pragma unroll
            for (int j = 0; j < 8; j++) {
                O[j][half * 2]     *= corr;
                O[j][half * 2 + 1] *= corr;
            }
        }

        // ---- O += P V (P fp16 from S regs; V fp16 hi) ----
#pragma unroll
        for (int ks = 0; ks < 4; ks++) {
            uint32_t pf[4];
            pf[0] = f2h2(S[2 * ks][0],     S[2 * ks][1]);
            pf[1] = f2h2(S[2 * ks][2],     S[2 * ks][3]);
            pf[2] = f2h2(S[2 * ks + 1][0], S[2 * ks + 1][1]);
            pf[3] = f2h2(S[2 * ks + 1][2], S[2 * ks + 1][3]);
#pragma unroll
            for (int j = 0; j < 8; j++) {
                uint2 vh = *(const uint2*)(Vhb + (j * 8 + g) * VSW + ks * 8 + 2 * t);
                mma_fp16(O[j], pf, vh);
            }
        }

        __syncthreads();
        if (it + 2 < NIT) attn_stage_kv(Ka, Kb, Vh, smBase, tid, it + 2);
    }

    // Epilogue: normalize, write (B, S, H*Dh).
    const int b = bh >> 4, h = bh & 15;
#pragma unroll
    for (int half = 0; half < 2; half++) {
        const float inv = 1.0f / l_i[half];
        const int q = q0 + wq + half * 8 + g;
        float* orow = out + (size_t)(b * SEQ + q) * NTOT + h * NHID;
#pragma unroll
        for (int j = 0; j < 8; j++) {
            float2 v = make_float2(O[j][half * 2] * inv, O[j][half * 2 + 1] * inv);
            *(float2*)(orow + j * 8 + 2 * t) = v;
        }
    }
}

// ---------------------------------------------------------------------------
extern "C" void kernel_launch(void* const* d_in, const int* in_sizes, int n_in,
                              void* d_out, int out_size)
{
    const float* xq = (const float*)d_in[0];
    const float* xk = (const float*)d_in[1];
    const float* xv = (const float*)d_in[2];
    const float* wq = (const float*)d_in[3];
    const float* bq = (const float*)d_in[4];
    const float* wk = (const float*)d_in[5];
    const float* bk = (const float*)d_in[6];
    const float* wv = (const float*)d_in[7];
    const float* bv = (const float*)d_in[8];
    float* out = (float*)d_out;

    cudaFuncSetAttribute(qkv_gemm_s8, cudaFuncAttributeMaxDynamicSharedMemorySize,
                         G8_SMEM_BYTES);
    cudaFuncSetAttribute(attn_s8, cudaFuncAttributeMaxDynamicSharedMemorySize,
                         ATT_SMEM_BYTES);

    prep_quant<<<PREP_BLOCKS, 256>>>(xq, xk, xv, wq, wk, wv);

    dim3 gg(NTOT / 128, MTOT / 64, 3);
    qkv_gemm_s8<<<gg, 512, G8_SMEM_BYTES>>>(bq, bk, bv);

    dim3 ga(SEQ / 128, BH);
    attn_s8<<<ga, 256, ATT_SMEM_BYTES>>>(out);
}